// round 12
// baseline (speedup 1.0000x reference)
#include <cuda_runtime.h>

// PeakSense: out[b,p] = sum_i exp(-0.5*(mass[b,i]-mu[p])^2 * exp(-lv[p])) * iv[b,i],
// terms with arg < -10 dropped. Masses sorted per batch -> per-peak window.
//
// R12 = R10 (best: ncu 9.15us) with parallelism doubled on both axes:
//   GROUPS 8->16 (2048 CTAs -> 8 resident CTAs/SM = 64 warps, ~100% occ)
//   LANES  8->16 (per-lane window work halves: ~4.5 elems -> unroll 2 + rem)
// Everything else identical: mass-only 16KB smem, iv from global (MLP via
// unroll), branchless 12+1 rank search, ex2.approx, no in-loop predicate.

#define PS_B 128
#define PS_L 4096
#define PS_N 256
#define GROUPS 16                         // blocks per batch
#define PEAKS_PER_BLOCK (PS_N / GROUPS)   // 16
#define LANES 16                          // lanes per peak
#define THREADS (PEAKS_PER_BLOCK * LANES) // 256
#define LOG2E 1.4426950408889634f

__device__ __forceinline__ float ex2_approx(float x) {
    float r;
    asm("ex2.approx.f32 %0, %1;" : "=f"(r) : "f"(x));
    return r;
}
__device__ __forceinline__ float sqrt_approx(float x) {
    float r;
    asm("sqrt.approx.f32 %0, %1;" : "=f"(r) : "f"(x));
    return r;
}

__global__ __launch_bounds__(THREADS)
void peaksense_kernel(const float* __restrict__ mu,
                      const float* __restrict__ lv,
                      const float* __restrict__ masses,
                      const float* __restrict__ intens,
                      float* __restrict__ out) {
    __shared__ float sm_mass[PS_L];       // 16 KB

    const int b    = blockIdx.y;
    const int tid  = threadIdx.x;
    const int p    = blockIdx.x * PEAKS_PER_BLOCK + (tid >> 4);
    const int q    = tid & 15;            // lane within peak group
    const int lane = tid & 31;

    // Stage this batch's masses into shared (float4, 4 per thread, MLP=4).
    {
        const float4* m4 = reinterpret_cast<const float4*>(masses + (size_t)b * PS_L);
        float4* s4 = reinterpret_cast<float4*>(sm_mass);
        #pragma unroll
        for (int i = tid; i < PS_L / 4; i += THREADS) s4[i] = m4[i];
    }

    const float* __restrict__ iv = intens + (size_t)b * PS_L;

    const float m  = mu[p];
    const float lj = lv[p];
    const float inv_s2 = __expf(-lj);      // 1/sigma^2 (MUFU)
    // R^2 = 20/inv_s2 = 20*exp(lv); approx sqrt with slight inflation.
    // Boundary terms weigh <= e^-10 vs outputs ~10 -> ~1e-6 rel noise.
    const float R   = sqrt_approx(20.0f * __expf(lj)) * 1.0002f + 1e-5f;
    const float lob = m - R;
    const float hib = m + R;

    __syncthreads();

    // Branchless rank search (verified R7/R8/R10). Lanes 0-7 of each 16-lane
    // peak group: first >= lob. Lanes 8-15: first > hib. 12 steps + correction.
    const bool  isLo   = (q < 8);
    const float target = isLo ? lob : hib;
    int pos = 0;
    #pragma unroll
    for (int s = PS_L / 2; s > 0; s >>= 1) {
        float v = sm_mass[pos + s - 1];
        bool adv = isLo ? (v < target) : (v <= target);
        pos += adv ? s : 0;
    }
    {
        float v = sm_mass[pos];
        bool adv = isLo ? (v < target) : (v <= target);
        pos += adv ? 1 : 0;
    }
    const int base = lane & ~15;          // first lane of this peak group
    const int lo = __shfl_sync(0xFFFFFFFF, pos, base + 0);
    const int hi = __shfl_sync(0xFFFFFFFF, pos, base + 8);

    // w = exp2(c2*d*d); no in-loop predicate (window tracks the -10 boundary
    // to ~0.002 mass units; boundary weight <= e^-10).
    const float c2 = -0.5f * inv_s2 * LOG2E;

    float acc0 = 0.0f, acc1 = 0.0f;
    int i = lo + q;
    #pragma unroll 1
    for (; i + LANES < hi; i += 2 * LANES) {
        float x0 = sm_mass[i];
        float x1 = sm_mass[i + LANES];
        float y0 = iv[i];
        float y1 = iv[i + LANES];
        float d0 = x0 - m, d1 = x1 - m;
        acc0 = fmaf(ex2_approx(c2 * d0 * d0), y0, acc0);
        acc1 = fmaf(ex2_approx(c2 * d1 * d1), y1, acc1);
    }
    if (i < hi) {
        float d = sm_mass[i] - m;
        acc0 = fmaf(ex2_approx(c2 * d * d), iv[i], acc0);
    }

    // Reduce the 16 lanes of this peak.
    float acc = acc0 + acc1;
    acc += __shfl_xor_sync(0xFFFFFFFF, acc, 1);
    acc += __shfl_xor_sync(0xFFFFFFFF, acc, 2);
    acc += __shfl_xor_sync(0xFFFFFFFF, acc, 4);
    acc += __shfl_xor_sync(0xFFFFFFFF, acc, 8);

    if (q == 0) out[(size_t)b * PS_N + p] = acc;
}

extern "C" void kernel_launch(void* const* d_in, const int* in_sizes, int n_in,
                              void* d_out, int out_size) {
    const float* mu     = (const float*)d_in[0];
    const float* lv     = (const float*)d_in[1];
    const float* masses = (const float*)d_in[2];
    const float* intens = (const float*)d_in[3];
    float* out = (float*)d_out;

    dim3 grid(GROUPS, PS_B);
    peaksense_kernel<<<grid, THREADS>>>(mu, lv, masses, intens, out);
}

// round 13
// speedup vs baseline: 1.4624x; 1.4624x over previous
#include <cuda_runtime.h>

// PeakSense: out[b,p] = sum_i exp(-0.5*(mass[b,i]-mu[p])^2 * exp(-lv[p])) * iv[b,i],
// terms with arg < -10 dropped. Masses sorted per batch -> per-peak window.
//
// R13 = R10 with the two measured overhead sources cut:
//  - search de-duplicated: threads 0-63 each run ONE branchless 12+1 search
//    (peak = t>>1, side = t&1), bounds shared via smem (R10 ran each x4).
//  - window vectorized x4: bounds rounded to multiples of 4; float4 loads from
//    smem mass + global iv. 8-lane group = 128B/wavefront: no bank conflicts,
//    4x fewer load instrs. Extra boundary elements weigh <= e^-10 (~4.5e-5) --
//    same no-predicate analysis as R10 (rel_err ~3e-7).
// Shape: GROUPS=8 (1024 CTAs), 256 thr, mass-only 16KB smem, ex2.approx.

#define PS_B 128
#define PS_L 4096
#define PS_N 256
#define GROUPS 8                          // blocks per batch
#define PEAKS_PER_BLOCK (PS_N / GROUPS)   // 32
#define LANES 8                           // lanes per peak
#define THREADS (PEAKS_PER_BLOCK * LANES) // 256
#define LOG2E 1.4426950408889634f

__device__ __forceinline__ float ex2_approx(float x) {
    float r;
    asm("ex2.approx.f32 %0, %1;" : "=f"(r) : "f"(x));
    return r;
}
__device__ __forceinline__ float sqrt_approx(float x) {
    float r;
    asm("sqrt.approx.f32 %0, %1;" : "=f"(r) : "f"(x));
    return r;
}

__global__ __launch_bounds__(THREADS)
void peaksense_kernel(const float* __restrict__ mu,
                      const float* __restrict__ lv,
                      const float* __restrict__ masses,
                      const float* __restrict__ intens,
                      float* __restrict__ out) {
    __shared__ float sm_mass[PS_L];               // 16 KB
    __shared__ int   sm_lo[PEAKS_PER_BLOCK];
    __shared__ int   sm_hi[PEAKS_PER_BLOCK];

    const int b     = blockIdx.y;
    const int tid   = threadIdx.x;
    const int g     = tid >> 3;                   // local peak index (0..31)
    const int q     = tid & 7;                    // lane within peak group
    const int pbase = blockIdx.x * PEAKS_PER_BLOCK;
    const int p     = pbase + g;

    // Stage this batch's masses into shared (float4, 4 per thread, MLP=4).
    {
        const float4* m4 = reinterpret_cast<const float4*>(masses + (size_t)b * PS_L);
        float4* s4 = reinterpret_cast<float4*>(sm_mass);
        #pragma unroll
        for (int i = tid; i < PS_L / 4; i += THREADS) s4[i] = m4[i];
    }

    const float* __restrict__ iv = intens + (size_t)b * PS_L;

    // Per-thread peak params (window phase).
    const float m  = mu[p];
    const float c2 = -0.5f * __expf(-lv[p]) * LOG2E;   // a = c2*d*d (log2 dom)

    __syncthreads();                                    // masses visible

    // De-duplicated search: 64 threads, one (peak, side) each.
    if (tid < 2 * PEAKS_PER_BLOCK) {
        const int  sg   = tid >> 1;                     // peak 0..31
        const bool isHi = tid & 1;
        const float mj = mu[pbase + sg];
        const float lj = lv[pbase + sg];
        // R^2 = 20*exp(lv); approx sqrt + inflation; boundary weight <= e^-10.
        const float R  = sqrt_approx(20.0f * __expf(lj)) * 1.0002f + 1e-5f;
        const float target = isHi ? (mj + R) : (mj - R);
        int pos = 0;
        #pragma unroll
        for (int s = PS_L / 2; s > 0; s >>= 1) {
            float v = sm_mass[pos + s - 1];
            bool adv = isHi ? (v <= target) : (v < target);
            pos += adv ? s : 0;
        }
        {
            float v = sm_mass[pos];
            bool adv = isHi ? (v <= target) : (v < target);
            pos += adv ? 1 : 0;
        }
        // Round outward to float4 granularity (extra elems weigh <= e^-10).
        if (isHi) sm_hi[sg] = (pos + 3) & ~3;
        else      sm_lo[sg] = pos & ~3;
    }

    __syncthreads();                                    // bounds visible

    const int lo4 = sm_lo[g];
    const int hi4 = sm_hi[g];

    // Vectorized window loop: lane q reads float4 at lo4+4q, stride 32 elems.
    // Group of 8 lanes = 128 consecutive bytes: 1 LDS.128 wavefront + 1 LDG
    // sector run per iteration. No predicate (see header).
    float acc0 = 0.0f, acc1 = 0.0f, acc2 = 0.0f, acc3 = 0.0f;
    #pragma unroll 1
    for (int i = lo4 + 4 * q; i < hi4; i += 4 * LANES) {
        float4 xm = *reinterpret_cast<const float4*>(sm_mass + i);
        float4 yv = *reinterpret_cast<const float4*>(iv + i);
        float d0 = xm.x - m, d1 = xm.y - m, d2 = xm.z - m, d3 = xm.w - m;
        acc0 = fmaf(ex2_approx(c2 * d0 * d0), yv.x, acc0);
        acc1 = fmaf(ex2_approx(c2 * d1 * d1), yv.y, acc1);
        acc2 = fmaf(ex2_approx(c2 * d2 * d2), yv.z, acc2);
        acc3 = fmaf(ex2_approx(c2 * d3 * d3), yv.w, acc3);
    }

    // Reduce the 8 lanes of this peak.
    float acc = (acc0 + acc1) + (acc2 + acc3);
    acc += __shfl_xor_sync(0xFFFFFFFF, acc, 1);
    acc += __shfl_xor_sync(0xFFFFFFFF, acc, 2);
    acc += __shfl_xor_sync(0xFFFFFFFF, acc, 4);

    if (q == 0) out[(size_t)b * PS_N + p] = acc;
}

extern "C" void kernel_launch(void* const* d_in, const int* in_sizes, int n_in,
                              void* d_out, int out_size) {
    const float* mu     = (const float*)d_in[0];
    const float* lv     = (const float*)d_in[1];
    const float* masses = (const float*)d_in[2];
    const float* intens = (const float*)d_in[3];
    float* out = (float*)d_out;

    dim3 grid(GROUPS, PS_B);
    peaksense_kernel<<<grid, THREADS>>>(mu, lv, masses, intens, out);
}